// round 12
// baseline (speedup 1.0000x reference)
#include <cuda_runtime.h>
#include <cuda_bf16.h>
#include <math.h>
#include <float.h>
#include <stdint.h>

// ---------------- problem constants ----------------
#define CB    2
#define CS    2048
#define CHID  1024
#define CH    16
#define CKVH  8
#define CHD   64
#define CQN   (CH * CHD)      // 1024
#define CKN   (CKVH * CHD)    // 512
#define CQK   1536
#define CBH   (CB * CH)       // 32
#define CSCALE 0.125f
#define CNEG  (-1000000000.0f)
#define KTH_IDX 715
#define QTR   128             // attention q-rows per CTA

// ---------------- scratch ----------------
__device__ float g_qk[CB * CS * CQK];
__device__ float g_v[CB * CS * CKN];
__device__ float g_q[CB * CS * CQN];
__device__ float g_k[CB * CS * CKN];
__device__ float g_attn[CB * CS * CQN];
__device__ float g_dyn[CB * CH * CS];
__device__ int   g_fu[CB * CH];

__device__ __align__(16) float g_hs_t[CB * CS * CHID];
__device__ __align__(16) float g_wqk_t[CQK * CHID];
__device__ __align__(16) float g_wo_t[CHID * CQN];
__device__ __align__(16) uint16_t g_hsh[CB * CS * CHID],   g_hsl[CB * CS * CHID];
__device__ __align__(16) uint16_t g_wvh[CKN * CHID],       g_wvl[CKN * CHID];
__device__ __align__(16) uint16_t g_qh[CB * CS * CQN],     g_ql[CB * CS * CQN];
__device__ __align__(16) uint16_t g_kh[CB * CS * CKN],     g_kl[CB * CS * CKN];
__device__ __align__(16) uint16_t g_vth[CB * CKVH * CHD * CS], g_vtl[CB * CKVH * CHD * CS];

// compacted (per (b,h)) K rows, V^T cols, bias, original indices, prefix counts
__device__ __align__(16) uint16_t g_kch[CBH * CS * CHD], g_kcl[CBH * CS * CHD];   // [bh][cidx][d]
__device__ __align__(16) uint16_t g_vcth[CBH * CHD * CS], g_vctl[CBH * CHD * CS]; // [bh][d][cidx]
__device__ float g_dync[CBH * CS];
__device__ int   g_oidx[CBH * CS];
__device__ int   g_c128[CBH * 16];

// ================= helpers =================
__device__ __forceinline__ uint32_t smem_u32(const void* p) {
    uint32_t a;
    asm("{ .reg .u64 t; cvta.to.shared.u64 t, %1; cvt.u32.u64 %0, t; }" : "=r"(a) : "l"(p));
    return a;
}
__device__ __forceinline__ void ldm_x4(uint32_t* r, uint32_t addr) {
    asm volatile("ldmatrix.sync.aligned.m8n8.x4.shared.b16 {%0,%1,%2,%3}, [%4];"
                 : "=r"(r[0]), "=r"(r[1]), "=r"(r[2]), "=r"(r[3]) : "r"(addr));
}
__device__ __forceinline__ void mma_bf16(float* c, const uint32_t* a, const uint32_t* b) {
    asm volatile(
        "mma.sync.aligned.m16n8k16.row.col.f32.bf16.bf16.f32 "
        "{%0,%1,%2,%3}, {%4,%5,%6,%7}, {%8,%9}, {%0,%1,%2,%3};"
        : "+f"(c[0]), "+f"(c[1]), "+f"(c[2]), "+f"(c[3])
        : "r"(a[0]), "r"(a[1]), "r"(a[2]), "r"(a[3]), "r"(b[0]), "r"(b[1]));
}
__device__ __forceinline__ void mma_tf32(float* c, const uint32_t* a, const uint32_t* b) {
    asm volatile(
        "mma.sync.aligned.m16n8k8.row.col.f32.tf32.tf32.f32 "
        "{%0,%1,%2,%3}, {%4,%5,%6,%7}, {%8,%9}, {%0,%1,%2,%3};"
        : "+f"(c[0]), "+f"(c[1]), "+f"(c[2]), "+f"(c[3])
        : "r"(a[0]), "r"(a[1]), "r"(a[2]), "r"(a[3]), "r"(b[0]), "r"(b[1]));
}
__device__ __forceinline__ uint32_t bf2(float e0, float e1) {
    uint32_t r;
    asm("cvt.rn.bf16x2.f32 %0, %1, %2;" : "=r"(r) : "f"(e1), "f"(e0));
    return r;
}
__device__ __forceinline__ float hif_lo(uint32_t h) { return __uint_as_float(h << 16); }
__device__ __forceinline__ float hif_hi(uint32_t h) { return __uint_as_float(h & 0xFFFF0000u); }
__device__ __forceinline__ float tf32r(float x) {
    uint32_t r;
    asm("cvt.rna.tf32.f32 %0, %1;" : "=r"(r) : "f"(x));
    return __uint_as_float(r);
}
__device__ __forceinline__ void cpa16(uint32_t dst, const void* src) {
    asm volatile("cp.async.cg.shared.global [%0], [%1], 16;" :: "r"(dst), "l"(src));
}
#define CP_COMMIT() asm volatile("cp.async.commit_group;" ::: "memory")
#define CP_WAIT(n)  asm volatile("cp.async.wait_group %0;" :: "n"(n) : "memory")

// ---------------- elementwise prep kernels ----------------
__global__ void tf32r_kernel(const float4* __restrict__ src, float4* __restrict__ dst, int n4) {
    int i = blockIdx.x * blockDim.x + threadIdx.x;
    if (i >= n4) return;
    float4 v = src[i];
    dst[i] = make_float4(tf32r(v.x), tf32r(v.y), tf32r(v.z), tf32r(v.w));
}
__global__ void split_kernel(const float4* __restrict__ src,
                             uint2* __restrict__ hi, uint2* __restrict__ lo, int n4) {
    int i = blockIdx.x * blockDim.x + threadIdx.x;
    if (i >= n4) return;
    float4 v = src[i];
    uint32_t h0 = bf2(v.x, v.y), h1 = bf2(v.z, v.w);
    uint32_t l0 = bf2(v.x - hif_lo(h0), v.y - hif_hi(h0));
    uint32_t l1 = bf2(v.z - hif_lo(h1), v.w - hif_hi(h1));
    hi[i] = make_uint2(h0, h1);
    lo[i] = make_uint2(l0, l1);
}

// ============ single-pass TF32 GEMM, BK=16 (R10 variant — fastest measured) ============
#define T32_TILE   10240
#define T32_STAGE  (2 * T32_TILE)
#define T32_SMEM   (2 * T32_STAGE)

__global__ void __launch_bounds__(256) tgemm32(const float* __restrict__ A,
                                               const float* __restrict__ W,
                                               float* __restrict__ C,
                                               int M, int N, int K) {
    extern __shared__ char sm[];
    const uint32_t sbase = smem_u32(sm);

    const int tid = threadIdx.x;
    const int wid = tid >> 5, lane = tid & 31;
    const int m0 = blockIdx.y * 128, n0 = blockIdx.x * 128;
    const int wm = wid & 1, wn = wid >> 1;

    const int lrow = tid >> 1;
    const int lh   = tid & 1;
    const size_t abase = (size_t)(m0 + lrow) * K + lh * 8;
    const size_t bbase = (size_t)(n0 + lrow) * K + lh * 8;
    const uint32_t doff = (uint32_t)(lrow * 80 + lh * 32);

    float acc[4][4][4];
#pragma unroll
    for (int i = 0; i < 4; ++i)
#pragma unroll
        for (int j = 0; j < 4; ++j)
#pragma unroll
            for (int q = 0; q < 4; ++q) acc[i][j][q] = 0.f;

    const int nchunk = K >> 4;

#define T32_STAGE_CHUNK(c, p)                                                  \
    do {                                                                       \
        const uint32_t d0 = sbase + (p) * T32_STAGE + doff;                    \
        const float* a_ = A + abase + (size_t)(c) * 16;                        \
        const float* b_ = W + bbase + (size_t)(c) * 16;                        \
        cpa16(d0, a_);              cpa16(d0 + 16, a_ + 4);                    \
        cpa16(d0 + T32_TILE, b_);   cpa16(d0 + T32_TILE + 16, b_ + 4);         \
    } while (0)

    T32_STAGE_CHUNK(0, 0);
    CP_COMMIT();

    for (int c = 0; c < nchunk; ++c) {
        const int p = c & 1;
        if (c + 1 < nchunk) {
            T32_STAGE_CHUNK(c + 1, p ^ 1);
            CP_COMMIT();
            CP_WAIT(1);
        } else {
            CP_WAIT(0);
        }
        __syncthreads();

        const uint32_t abuf = sbase + p * T32_STAGE;
        const uint32_t bbuf = abuf + T32_TILE;

        uint32_t bf[4][4];
#pragma unroll
        for (int nf = 0; nf < 4; ++nf) {
            const uint32_t rowb = (uint32_t)(wn * 32 + nf * 8 + (lane & 7));
            const uint32_t addr = bbuf + rowb * 80 + (uint32_t)(lane >> 3) * 16;
            ldm_x4(bf[nf], addr);
        }
#pragma unroll
        for (int ks = 0; ks < 2; ++ks) {
#pragma unroll
            for (int mf = 0; mf < 4; ++mf) {
                const uint32_t rowa = (uint32_t)(wm * 64 + mf * 16 + (lane & 15));
                const uint32_t addr = abuf + rowa * 80 + ks * 32 + (uint32_t)((lane >> 4) << 4);
                uint32_t af[4];
                ldm_x4(af, addr);
#pragma unroll
                for (int nf = 0; nf < 4; ++nf)
                    mma_tf32(acc[mf][nf], af, bf[nf] + ks * 2);
            }
        }
        __syncthreads();
    }

#pragma unroll
    for (int mf = 0; mf < 4; ++mf) {
        const int row = m0 + wm * 64 + mf * 16 + (lane >> 2);
#pragma unroll
        for (int nf = 0; nf < 4; ++nf) {
            const int col = n0 + wn * 32 + nf * 8 + (lane & 3) * 2;
            *(float2*)(C + (size_t)row * N + col)       = make_float2(acc[mf][nf][0], acc[mf][nf][1]);
            *(float2*)(C + (size_t)(row + 8) * N + col) = make_float2(acc[mf][nf][2], acc[mf][nf][3]);
        }
    }
}

// ============ bf16x3 GEMM (pre-split, cp.async) ============
#define BG_TILE   10240
#define BG_STAGE  (4 * BG_TILE)
#define BG_SMEM   (2 * BG_STAGE)

__global__ void __launch_bounds__(256) bgemm_nt(const uint16_t* __restrict__ Ah,
                                                const uint16_t* __restrict__ Al,
                                                const uint16_t* __restrict__ Bh,
                                                const uint16_t* __restrict__ Bl,
                                                float* __restrict__ C,
                                                int M, int N, int K) {
    extern __shared__ char sm[];
    const uint32_t sbase = smem_u32(sm);

    const int tid = threadIdx.x;
    const int wid = tid >> 5, lane = tid & 31;
    const int m0 = blockIdx.y * 128, n0 = blockIdx.x * 128;
    const int wm = wid & 1, wn = wid >> 1;

    const int lrow = tid >> 1;
    const int lh   = tid & 1;
    const size_t abase = (size_t)(m0 + lrow) * K + lh * 16;
    const size_t bbase = (size_t)(n0 + lrow) * K + lh * 16;
    const uint32_t doff = (uint32_t)(lrow * 80 + lh * 32);

    float acc[4][4][4];
#pragma unroll
    for (int i = 0; i < 4; ++i)
#pragma unroll
        for (int j = 0; j < 4; ++j)
#pragma unroll
            for (int q = 0; q < 4; ++q) acc[i][j][q] = 0.f;

    const int nchunk = K >> 5;

#define BG_STAGE_CHUNK(c, p)                                                   \
    do {                                                                       \
        const uint32_t d0 = sbase + (p) * BG_STAGE + doff;                     \
        const uint16_t* a_h = Ah + abase + (size_t)(c) * 32;                   \
        const uint16_t* a_l = Al + abase + (size_t)(c) * 32;                   \
        const uint16_t* b_h = Bh + bbase + (size_t)(c) * 32;                   \
        const uint16_t* b_l = Bl + bbase + (size_t)(c) * 32;                   \
        cpa16(d0, a_h);                  cpa16(d0 + 16, a_h + 8);              \
        cpa16(d0 + BG_TILE, a_l);        cpa16(d0 + BG_TILE + 16, a_l + 8);    \
        cpa16(d0 + 2 * BG_TILE, b_h);    cpa16(d0 + 2 * BG_TILE + 16, b_h + 8);\
        cpa16(d0 + 3 * BG_TILE, b_l);    cpa16(d0 + 3 * BG_TILE + 16, b_l + 8);\
    } while (0)

    BG_STAGE_CHUNK(0, 0);
    CP_COMMIT();

    for (int c = 0; c < nchunk; ++c) {
        const int p = c & 1;
        if (c + 1 < nchunk) {
            BG_STAGE_CHUNK(c + 1, p ^ 1);
            CP_COMMIT();
            CP_WAIT(1);
        } else {
            CP_WAIT(0);
        }
        __syncthreads();

        const uint32_t buf = sbase + p * BG_STAGE;
#pragma unroll
        for (int ks = 0; ks < 2; ++ks) {
            const int kk = ks * 16;
            uint32_t bh[4][2], bl[4][2];
#pragma unroll
            for (int half = 0; half < 2; ++half) {
                const int n = wn * 32 + half * 16;
                const uint32_t rowb = (uint32_t)(n + (lane & 7) + ((lane & 16) >> 1));
                const uint32_t colb = (uint32_t)(kk + (lane & 8));
                const uint32_t addr = buf + 2 * BG_TILE + rowb * 80 + colb * 2;
                uint32_t r[4];
                ldm_x4(r, addr);
                bh[half * 2][0] = r[0]; bh[half * 2][1] = r[1];
                bh[half * 2 + 1][0] = r[2]; bh[half * 2 + 1][1] = r[3];
                ldm_x4(r, addr + BG_TILE);
                bl[half * 2][0] = r[0]; bl[half * 2][1] = r[1];
                bl[half * 2 + 1][0] = r[2]; bl[half * 2 + 1][1] = r[3];
            }
#pragma unroll
            for (int mf = 0; mf < 4; ++mf) {
                const int m = wm * 64 + mf * 16;
                const uint32_t rowa = (uint32_t)(m + (lane & 15));
                const uint32_t cola = (uint32_t)(kk + ((lane >> 4) << 3));
                const uint32_t addr = buf + rowa * 80 + cola * 2;
                uint32_t ah4[4], al4[4];
                ldm_x4(ah4, addr);
                ldm_x4(al4, addr + BG_TILE);
#pragma unroll
                for (int nf = 0; nf < 4; ++nf) {
                    mma_bf16(acc[mf][nf], ah4, bh[nf]);
                    mma_bf16(acc[mf][nf], ah4, bl[nf]);
                    mma_bf16(acc[mf][nf], al4, bh[nf]);
                }
            }
        }
        __syncthreads();
    }

#pragma unroll
    for (int mf = 0; mf < 4; ++mf) {
        const int row = m0 + wm * 64 + mf * 16 + (lane >> 2);
#pragma unroll
        for (int nf = 0; nf < 4; ++nf) {
            const int col = n0 + wn * 32 + nf * 8 + (lane & 3) * 2;
            *(float2*)(C + (size_t)row * N + col)       = make_float2(acc[mf][nf][0], acc[mf][nf][1]);
            *(float2*)(C + (size_t)(row + 8) * N + col) = make_float2(acc[mf][nf][2], acc[mf][nf][3]);
        }
    }
}

// ---------------- V transpose + split ----------------
__global__ void __launch_bounds__(256) vtrans_kernel() {
    __shared__ float t[32][33];
    const int bk = blockIdx.z, b = bk >> 3, kvh = bk & 7;
    const int s0 = blockIdx.x * 32, d0 = blockIdx.y * 32;
    const int x = threadIdx.x & 31, y = threadIdx.x >> 5;
#pragma unroll
    for (int j = 0; j < 4; ++j) {
        int s = s0 + y + j * 8;
        t[y + j * 8][x] = g_v[((size_t)(b * CS + s)) * CKN + kvh * CHD + d0 + x];
    }
    __syncthreads();
#pragma unroll
    for (int j = 0; j < 4; ++j) {
        int d = d0 + y + j * 8;
        float v = t[x][y + j * 8];
        uint32_t hv = bf2(v, 0.f);
        uint32_t lv = bf2(v - hif_lo(hv), 0.f);
        size_t idx = (((size_t)(b * CKVH + kvh)) * CHD + d) * CS + s0 + x;
        g_vth[idx] = (uint16_t)(hv & 0xFFFFu);
        g_vtl[idx] = (uint16_t)(lv & 0xFFFFu);
    }
}

// ---------------- RoPE ----------------
__global__ void rope_kernel(const float* __restrict__ cosp,
                            const float* __restrict__ sinp) {
    int idx = blockIdx.x * blockDim.x + threadIdx.x;
    int d  = idx & 31;
    int t  = idx >> 5;
    int hh = t % 24;
    int t2 = t / 24;
    int s  = t2 % CS;
    int b  = t2 / CS;

    const float* cb = cosp + ((size_t)b * CS + s) * CHD;
    const float* sb = sinp + ((size_t)b * CS + s) * CHD;
    float c1 = cb[d],      s1 = sb[d];
    float c2 = cb[d + 32], s2 = sb[d + 32];

    const float* src;
    float* dst;
    uint16_t *bh, *bl;
    const size_t row = ((size_t)b * CS + s) * CQK;
    if (hh < CH) {
        src = g_qk + row + hh * CHD;
        size_t off = ((size_t)b * CS + s) * CQN + hh * CHD;
        dst = g_q + off; bh = g_qh + off; bl = g_ql + off;
    } else {
        src = g_qk + row + 1024 + (hh - CH) * CHD;
        size_t off = ((size_t)b * CS + s) * CKN + (hh - CH) * CHD;
        dst = g_k + off; bh = g_kh + off; bl = g_kl + off;
    }

    float x1 = src[d];
    float x2 = src[d + 32];
    float y1 = x1 * c1 - x2 * s1;
    float y2 = x2 * c2 + x1 * s2;
    dst[d]      = y1;
    dst[d + 32] = y2;

    uint32_t h1 = bf2(y1, 0.f);
    uint32_t h2 = bf2(y2, 0.f);
    bh[d]      = (uint16_t)(h1 & 0xFFFFu);
    bh[d + 32] = (uint16_t)(h2 & 0xFFFFu);
    bl[d]      = (uint16_t)(bf2(y1 - hif_lo(h1), 0.f) & 0xFFFFu);
    bl[d + 32] = (uint16_t)(bf2(y2 - hif_lo(h2), 0.f) & 0xFFFFu);
}

// ---------------- dt -> dyn ----------------
__global__ void __launch_bounds__(256) dt_kernel(const float* __restrict__ Wdt,
                                                 const float* __restrict__ Avec) {
    __shared__ float vsh[CKN];
    int bs = blockIdx.x;
    int b = bs / CS, s = bs % CS;
    int tid = threadIdx.x;
    vsh[tid]        = g_v[(size_t)bs * CKN + tid];
    vsh[tid + 256]  = g_v[(size_t)bs * CKN + tid + 256];
    __syncthreads();

    int warp = tid >> 5, lane = tid & 31;
    for (int h = warp; h < CH; h += 8) {
        const float* wrow = Wdt + (size_t)h * CKN;
        float acc = 0.f;
        for (int j = lane; j < CKN; j += 32) acc = fmaf(vsh[j], wrow[j], acc);
#pragma unroll
        for (int off = 16; off > 0; off >>= 1)
            acc += __shfl_down_sync(0xffffffffu, acc, off);
        if (lane == 0) {
            float x = acc;
            float sp = fmaxf(x, 0.f) + log1pf(expf(-fabsf(x)));
            g_dyn[((size_t)b * CH + h) * CS + s] = expf(Avec[h] * sp);
        }
    }
}

// ---------------- rate kernel ----------------
__global__ void __launch_bounds__(256) rate_kernel() {
    __shared__ float sv[CS];
    __shared__ float s_rate;
    __shared__ int   s_fu;
    int bh = blockIdx.x;
    int tid = threadIdx.x;
    float* dptr = g_dyn + (size_t)bh * CS;

    for (int i = tid; i < CS; i += 256) sv[i] = dptr[i];
    __syncthreads();

    for (int k = 2; k <= CS; k <<= 1) {
        for (int j = k >> 1; j > 0; j >>= 1) {
            for (int i = tid; i < CS; i += 256) {
                int ixj = i ^ j;
                if (ixj > i) {
                    float a = sv[i], c = sv[ixj];
                    bool up = ((i & k) == 0);
                    if (up ? (a > c) : (a < c)) { sv[i] = c; sv[ixj] = a; }
                }
            }
            __syncthreads();
        }
    }
    if (tid == 0) { s_rate = sv[KTH_IDX]; s_fu = CS; }
    __syncthreads();

    float rate = s_rate;
    for (int i = tid; i < CS; i += 256) {
        float m = dptr[i];
        if (m < rate) dptr[i] = -FLT_MAX;
        else          atomicMin(&s_fu, i);
    }
    __syncthreads();
    if (tid == 0) g_fu[bh] = s_fu;
}

// ---------------- compaction: gather unmasked keys per (b,h) ----------------
__global__ void __launch_bounds__(256) compact_kernel() {
    __shared__ int tsum[256];
    __shared__ int s_total;
    const int bh = blockIdx.x;
    const int b = bh >> 4, h = bh & 15, kvh = h >> 1;
    const int tid = threadIdx.x;
    const float* dptr = g_dyn + (size_t)bh * CS;

    // per-thread chunk of 8 keys: flags + local prefix
    const int base = tid * 8;
    int loc[8];
    int cnt = 0;
#pragma unroll
    for (int j = 0; j < 8; ++j) {
        loc[j] = cnt;
        cnt += (dptr[base + j] != -FLT_MAX) ? 1 : 0;
    }
    tsum[tid] = cnt;
    __syncthreads();
    // inclusive scan (Hillis-Steele)
    for (int off = 1; off < 256; off <<= 1) {
        int v = (tid >= off) ? tsum[tid - off] : 0;
        __syncthreads();
        tsum[tid] += v;
        __syncthreads();
    }
    if (tid == 255) s_total = tsum[255];
    if (tid < 16) g_c128[bh * 16 + tid] = tsum[(tid + 1) * 16 - 1];
    const int excl = tsum[tid] - cnt;
    __syncthreads();

    // phase 1: scatter K rows + bias + original index
#pragma unroll
    for (int j = 0; j < 8; ++j) {
        const int i = base + j;
        const float dv = dptr[i];
        if (dv != -FLT_MAX) {
            const int cidx = excl + loc[j];
            g_oidx[(size_t)bh * CS + cidx] = i;
            g_dync[(size_t)bh * CS + cidx] = dv;
            const uint4* sh = (const uint4*)(g_kh + ((size_t)(b * CS + i)) * CKN + kvh * CHD);
            const uint4* sl = (const uint4*)(g_kl + ((size_t)(b * CS + i)) * CKN + kvh * CHD);
            uint4* dh = (uint4*)(g_kch + ((size_t)bh * CS + cidx) * CHD);
            uint4* dl = (uint4*)(g_kcl + ((size_t)bh * CS + cidx) * CHD);
#pragma unroll
            for (int q = 0; q < 8; ++q) { dh[q] = sh[q]; dl[q] = sl[q]; }
        }
    }
    __syncthreads();

    const int total = s_total;
    int padend = (total + 63) & ~63;
    if (padend > CS) padend = CS;

    // phase 2: zero-pad tail K rows + sentinel idx/bias
    for (int cidx = total + tid; cidx < padend; cidx += 256) {
        g_oidx[(size_t)bh * CS + cidx] = 0x7FFFFFFF;
        g_dync[(size_t)bh * CS + cidx] = -FLT_MAX;
        uint4 z = make_uint4(0, 0, 0, 0);
        uint4* dh = (uint4*)(g_kch + ((size_t)bh * CS + cidx) * CHD);
        uint4* dl = (uint4*)(g_kcl + ((size_t)bh * CS + cidx) * CHD);
#pragma unroll
        for (int q = 0; q < 8; ++q) { dh[q] = z; dl[q] = z; }
    }

    // phase 3: gather V^T columns (zeros for padding)
    const int nvt = CHD * padend;
    for (int x = tid; x < nvt; x += 256) {
        const int d = x / padend;
        const int cidx = x - d * padend;
        const size_t dst = ((size_t)bh * CHD + d) * CS + cidx;
        if (cidx < total) {
            const int i = g_oidx[(size_t)bh * CS + cidx];
            const size_t src = (((size_t)(b * CKVH + kvh)) * CHD + d) * CS + i;
            g_vcth[dst] = g_vth[src];
            g_vctl[dst] = g_vtl[src];
        } else {
            g_vcth[dst] = 0;
            g_vctl[dst] = 0;
        }
    }
}

// ---------------- attention over compacted keys ----------------
// smem: K[2][hi,lo] 36864 @0, V[2][hi,lo] 36864 @36864, mb[2][64] @73728, idx[2][64] @74240
#define AT_SMEM 74752

__global__ void __launch_bounds__(256) attn_mma_kernel() {
    extern __shared__ char asmem[];
    const uint32_t ksb = smem_u32(asmem);
    const uint32_t vsb = ksb + 36864;
    float* smb = (float*)(asmem + 73728);
    int* sidx = (int*)(asmem + 74240);

    const int tid = threadIdx.x, lane = tid & 31, w = tid >> 5;
    const int qt = (CS / QTR - 1) - blockIdx.x;
    const int bh = blockIdx.y;
    const int b = bh >> 4, h = bh & 15;
    const int cnt = g_c128[bh * 16 + qt];
    const int nkt = (cnt + 63) >> 6;

    const int srow = tid & 63, part4 = tid >> 6;
    const uint32_t soff = (uint32_t)(srow * 144 + part4 * 32);

    const uint16_t* ksrc_h = g_kch + ((size_t)bh * CS + srow) * CHD + part4 * 16;
    const uint16_t* ksrc_l = g_kcl + ((size_t)bh * CS + srow) * CHD + part4 * 16;
    const uint16_t* vsrc_h = g_vcth + ((size_t)bh * CHD + srow) * CS + part4 * 16;
    const uint16_t* vsrc_l = g_vctl + ((size_t)bh * CHD + srow) * CS + part4 * 16;

#define AT_STAGE_KV(kt, p)                                                        \
    do {                                                                          \
        const uint16_t* kh_ = ksrc_h + (size_t)(kt) * 64 * CHD;                   \
        const uint16_t* kl_ = ksrc_l + (size_t)(kt) * 64 * CHD;                   \
        const uint16_t* vh_ = vsrc_h + (kt) * 64;                                 \
        const uint16_t* vl_ = vsrc_l + (kt) * 64;                                 \
        uint32_t kd = ksb + (p) * 18432 + soff;                                   \
        uint32_t vd = vsb + (p) * 18432 + soff;                                   \
        cpa16(kd, kh_);         cpa16(kd + 16, kh_ + 8);                          \
        cpa16(kd + 9216, kl_);  cpa16(kd + 9216 + 16, kl_ + 8);                   \
        cpa16(vd, vh_);         cpa16(vd + 16, vh_ + 8);                          \
        cpa16(vd + 9216, vl_);  cpa16(vd + 9216 + 16, vl_ + 8);                   \
    } while (0)

    // ---- stage Q (hi -> K buf1, lo -> V buf1) + compacted K/V tile 0 ----
    {
        const int qrow = tid >> 1, qpart = tid & 1;
        const uint32_t qoff = (uint32_t)(qrow * 144 + qpart * 64);
        const uint16_t* qh_ = g_qh + ((size_t)(b * CS + qt * QTR + qrow)) * CQN + h * CHD + qpart * 32;
        const uint16_t* ql_ = g_ql + ((size_t)(b * CS + qt * QTR + qrow)) * CQN + h * CHD + qpart * 32;
        uint32_t qdh = ksb + 18432 + qoff;
        uint32_t qdl = vsb + 18432 + qoff;
        cpa16(qdh, qh_);        cpa16(qdh + 16, qh_ + 8);
        cpa16(qdh + 32, qh_ + 16); cpa16(qdh + 48, qh_ + 24);
        cpa16(qdl, ql_);        cpa16(qdl + 16, ql_ + 8);
        cpa16(qdl + 32, ql_ + 16); cpa16(qdl + 48, ql_ + 24);
    }
    AT_STAGE_KV(0, 0);
    CP_COMMIT();
    if (tid < 64) {
        smb[tid] = g_dync[(size_t)bh * CS + tid];
        sidx[tid] = g_oidx[(size_t)bh * CS + tid];
    }
    CP_WAIT(0);
    __syncthreads();

    // ---- Q fragments ----
    uint32_t qhf[4][4], qlf[4][4];
    {
        const uint32_t rowa = (uint32_t)(w * 16 + (lane & 15));
        const uint32_t cola0 = (uint32_t)((lane >> 4) << 3);
#pragma unroll
        for (int ks = 0; ks < 4; ++ks) {
            const uint32_t off = rowa * 144 + (ks * 16 + cola0) * 2;
            ldm_x4(qhf[ks], ksb + 18432 + off);
            ldm_x4(qlf[ks], vsb + 18432 + off);
        }
    }
    __syncthreads();

    float oacc[8][4];
#pragma unroll
    for (int nf = 0; nf < 8; ++nf)
#pragma unroll
        for (int j = 0; j < 4; ++j) oacc[nf][j] = 0.f;

    float mrun0 = -1e30f, mrun1 = -1e30f, lrun0 = 0.f, lrun1 = 0.f;
    const int row0 = lane >> 2;
    const int gqi0 = qt * QTR + w * 16 + row0, gqi1 = gqi0 + 8;   // global q rows

    for (int kt = 0; kt < nkt; ++kt) {
        const int p = kt & 1;
        if (kt + 1 < nkt) {
            AT_STAGE_KV(kt + 1, p ^ 1);
            CP_COMMIT();
            if (tid < 64) {
                smb[(p ^ 1) * 64 + tid] = g_dync[(size_t)bh * CS + (kt + 1) * 64 + tid];
                sidx[(p ^ 1) * 64 + tid] = g_oidx[(size_t)bh * CS + (kt + 1) * 64 + tid];
            }
            CP_WAIT(1);
        } else {
            CP_WAIT(0);
        }
        __syncthreads();

        const uint32_t kbuf = ksb + p * 18432;
        const uint32_t vbuf = vsb + p * 18432;
        const float* mbp = smb + p * 64;
        const int* idxp = sidx + p * 64;

        // ---- S = Q @ K^T ----
        float sc[8][4];
#pragma unroll
        for (int nf = 0; nf < 8; ++nf)
#pragma unroll
            for (int j = 0; j < 4; ++j) sc[nf][j] = 0.f;

#pragma unroll
        for (int ks = 0; ks < 4; ++ks) {
#pragma unroll
            for (int g = 0; g < 4; ++g) {
                const uint32_t rowb = (uint32_t)(g * 16 + (lane & 7) + ((lane & 16) >> 1));
                const uint32_t colb = (uint32_t)(ks * 16 + (lane & 8));
                const uint32_t addr = kbuf + rowb * 144 + colb * 2;
                uint32_t kh4[4], kl4[4];
                ldm_x4(kh4, addr);
                ldm_x4(kl4, addr + 9216);
                mma_bf16(sc[2 * g],     qhf[ks], kh4);
                mma_bf16(sc[2 * g],     qhf[ks], kl4);
                mma_bf16(sc[2 * g],     qlf[ks], kh4);
                mma_bf16(sc[2 * g + 1], qhf[ks], kh4 + 2);
                mma_bf16(sc[2 * g + 1], qhf[ks], kl4 + 2);
                mma_bf16(sc[2 * g + 1], qlf[ks], kh4 + 2);
            }
        }

        // ---- online softmax with per-key original-index causal mask ----
        float mx0 = -1e30f, mx1 = -1e30f;
#pragma unroll
        for (int nf = 0; nf < 8; ++nf) {
            const int c0 = nf * 8 + (lane & 3) * 2;
            const float b0 = mbp[c0], b1 = mbp[c0 + 1];
            const int i0 = idxp[c0], i1 = idxp[c0 + 1];
            float s00 = sc[nf][0] * CSCALE + b0;
            float s01 = sc[nf][1] * CSCALE + b1;
            float s10 = sc[nf][2] * CSCALE + b0;
            float s11 = sc[nf][3] * CSCALE + b1;
            if (i0 > gqi0) s00 = -FLT_MAX;
            if (i1 > gqi0) s01 = -FLT_MAX;
            if (i0 > gqi1) s10 = -FLT_MAX;
            if (i1 > gqi1) s11 = -FLT_MAX;
            sc[nf][0] = s00; sc[nf][1] = s01; sc[nf][2] = s10; sc[nf][3] = s11;
            mx0 = fmaxf(mx0, fmaxf(s00, s01));
            mx1 = fmaxf(mx1, fmaxf(s10, s11));
        }
        mx0 = fmaxf(mx0, __shfl_xor_sync(0xffffffffu, mx0, 1));
        mx0 = fmaxf(mx0, __shfl_xor_sync(0xffffffffu, mx0, 2));
        mx1 = fmaxf(mx1, __shfl_xor_sync(0xffffffffu, mx1, 1));
        mx1 = fmaxf(mx1, __shfl_xor_sync(0xffffffffu, mx1, 2));

        const float mn0 = fmaxf(mrun0, mx0), mn1 = fmaxf(mrun1, mx1);
        const float esc0 = __expf(mrun0 - mn0), esc1 = __expf(mrun1 - mn1);
        mrun0 = mn0; mrun1 = mn1;

        float sum0 = 0.f, sum1 = 0.f;
#pragma unroll
        for (int nf = 0; nf < 8; ++nf) {
            float p00 = __expf(sc[nf][0] - mn0);
            float p01 = __expf(sc[nf][1] - mn0);
            float p10 = __expf(sc[nf][2] - mn1);
            float p11 = __expf(sc[nf][3] - mn1);
            sc[nf][0] = p00; sc[nf][1] = p01; sc[nf][2] = p10; sc[nf][3] = p11;
            sum0 += p00 + p01;
            sum1 += p10 + p11;
        }
        sum0 += __shfl_xor_sync(0xffffffffu, sum0, 1);
        sum0 += __shfl_xor_sync(0xffffffffu, sum0, 2);
        sum1 += __shfl_xor_sync(0xffffffffu, sum1, 1);
        sum1 += __shfl_xor_sync(0xffffffffu, sum1, 2);
        lrun0 = lrun0 * esc0 + sum0;
        lrun1 = lrun1 * esc1 + sum1;

#pragma unroll
        for (int nf = 0; nf < 8; ++nf) {
            oacc[nf][0] *= esc0; oacc[nf][1] *= esc0;
            oacc[nf][2] *= esc1; oacc[nf][3] *= esc1;
        }

        // ---- O += P @ V ----
#pragma unroll
        for (int ks = 0; ks < 4; ++ks) {
            uint32_t ah4[4], al4[4];
            ah4[0] = bf2(sc[2 * ks][0], sc[2 * ks][1]);
            ah4[1] = bf2(sc[2 * ks][2], sc[2 * ks][3]);
            ah4[2] = bf2(sc[2 * ks + 1][0], sc[2 * ks + 1][1]);
            ah4[3] = bf2(sc[2 * ks + 1][2], sc[2 * ks + 1][3]);
            al4[0] = bf2(sc[2 * ks][0] - hif_lo(ah4[0]), sc[2 * ks][1] - hif_hi(ah4[0]));
            al4[1] = bf2(sc[2 * ks][2] - hif_lo(ah4[1]), sc[2 * ks][3] - hif_hi(ah4[1]));
            al4[2] = bf2(sc[2 * ks + 1][0] - hif_lo(ah4[2]), sc[2 * ks + 1][1] - hif_hi(ah4[2]));
            al4[3] = bf2(sc[2 * ks + 1][2] - hif_lo(ah4[3]), sc[2 * ks + 1][3] - hif_hi(ah4[3]));
#pragma unroll
            for (int g = 0; g < 4; ++g) {
                const uint32_t rowb = (uint32_t)(g * 16 + (lane & 7) + ((lane & 16) >> 1));
                const uint32_t colb = (uint32_t)(ks * 16 + (lane & 8));
                const uint32_t addr = vbuf + rowb * 144 + colb * 2;
                uint32_t vh4[4], vl4[4];
                ldm_x4(vh4, addr);
                ldm_x4(vl4, addr + 9216);
                mma_bf16(oacc[2 * g],     ah4, vh4);
                mma_bf16(oacc[2 * g],     ah4, vl4);
                mma_bf16(oacc[2 * g],     al4, vh4);
                mma_bf16(oacc[2 * g + 1], ah4, vh4 + 2);
                mma_bf16(oacc[2 * g + 1], ah4, vl4 + 2);
                mma_bf16(oacc[2 * g + 1], al4, vh4 + 2);
            }
        }
        __syncthreads();
    }

    // ---- epilogue ----
    const float inv0 = 1.f / lrun0, inv1 = 1.f / lrun1;
    const int grow0 = qt * QTR + w * 16 + row0;
    float* ob0 = g_attn + ((size_t)(b * CS + grow0)) * CQN + h * CHD;
    float* ob1 = g_attn + ((size_t)(b * CS + grow0 + 8)) * CQN + h * CHD;
#pragma unroll
    for (int nf = 0; nf < 8; ++nf) {
        const int col = nf * 8 + (lane & 3) * 2;
        *(float2*)(ob0 + col) = make_float2(tf32r(oacc[nf][0] * inv0), tf32r(oacc[nf][1] * inv0));
        *(float2*)(ob1 + col) = make_float2(tf32r(oacc[nf][2] * inv1), tf32r(oacc[nf][3] * inv1));
    }
}

// ---------------- exact full-row fixup ----------------
__global__ void __launch_bounds__(256) fixup_kernel() {
    __shared__ float qrow[CHD];
    __shared__ float s_sh[CS];
    __shared__ float red[256];
    __shared__ float s_max, s_den;

    int bh = blockIdx.x;
    int b = bh >> 4, h = bh & 15, kvh = h >> 1;
    int tid = threadIdx.x;
    int fu = g_fu[bh];
    if (fu <= 0) return;

    for (int qi = 0; qi < fu; ++qi) {
        if (tid < CHD) qrow[tid] = g_q[((size_t)(b * CS + qi)) * CQN + h * CHD + tid];
        __syncthreads();

        float lm = -FLT_MAX;
        for (int ki = tid; ki < CS; ki += 256) {
            const float* krow = g_k + ((size_t)(b * CS + ki)) * CKN + kvh * CHD;
            float dot = 0.f;
#pragma unroll 16
            for (int d = 0; d < CHD; ++d) dot = fmaf(qrow[d], krow[d], dot);
            float mv = g_dyn[(size_t)bh * CS + ki] + ((ki <= qi) ? 0.0f : CNEG);
            float sc = dot * CSCALE + mv;
            s_sh[ki] = sc;
            lm = fmaxf(lm, sc);
        }
        red[tid] = lm;
        __syncthreads();
        for (int off = 128; off > 0; off >>= 1) {
            if (tid < off) red[tid] = fmaxf(red[tid], red[tid + off]);
            __syncthreads();
        }
        if (tid == 0) s_max = red[0];
        __syncthreads();

        float ls = 0.f;
        float rmax = s_max;
        for (int ki = tid; ki < CS; ki += 256) {
            float w2 = expf(s_sh[ki] - rmax);
            s_sh[ki] = w2;
            ls += w2;
        }
        red[tid] = ls;
        __syncthreads();
        for (int off = 128; off > 0; off >>= 1) {
            if (tid < off) red[tid] += red[tid + off];
            __syncthreads();
        }
        if (tid == 0) s_den = red[0];
        __syncthreads();

        int d = tid & 63, part = tid >> 6;
        float oacc = 0.f;
        for (int ki = part; ki < CS; ki += 4)
            oacc = fmaf(s_sh[ki], g_v[((size_t)(b * CS + ki)) * CKN + kvh * CHD + d], oacc);
        red[tid] = oacc;
        __syncthreads();
        if (tid < 64) {
            float tot = (red[tid] + red[tid + 64] + red[tid + 128] + red[tid + 192]) / s_den;
            g_attn[((size_t)(b * CS + qi)) * CQN + h * CHD + d] = tf32r(tot);
        }
        __syncthreads();
    }
}

// ---------------- host launcher (forked-stream graph) ----------------
static void launch_tgemm32(cudaStream_t st, const float* A, const float* W, float* C,
                           int M, int N, int K) {
    cudaFuncSetAttribute(tgemm32, cudaFuncAttributeMaxDynamicSharedMemorySize, T32_SMEM);
    tgemm32<<<dim3(N / 128, M / 128), 256, T32_SMEM, st>>>(A, W, C, M, N, K);
}
static void launch_bgemm(cudaStream_t st, const uint16_t* Ah, const uint16_t* Al,
                         const uint16_t* Bh, const uint16_t* Bl,
                         float* C, int M, int N, int K) {
    cudaFuncSetAttribute(bgemm_nt, cudaFuncAttributeMaxDynamicSharedMemorySize, BG_SMEM);
    bgemm_nt<<<dim3(N / 128, M / 128), 256, BG_SMEM, st>>>(Ah, Al, Bh, Bl, C, M, N, K);
}
static void launch_tf32r(cudaStream_t st, const float* src, float* dst, int n) {
    int n4 = n / 4;
    tf32r_kernel<<<(n4 + 255) / 256, 256, 0, st>>>((const float4*)src, (float4*)dst, n4);
}
static void launch_split(cudaStream_t st, const float* src, uint16_t* hi, uint16_t* lo, int n) {
    int n4 = n / 4;
    split_kernel<<<(n4 + 255) / 256, 256, 0, st>>>((const float4*)src, (uint2*)hi, (uint2*)lo, n4);
}

extern "C" void kernel_launch(void* const* d_in, const int* in_sizes, int n_in,
                              void* d_out, int out_size) {
    const float* hs   = (const float*)d_in[0];
    const float* cosp = (const float*)d_in[1];
    const float* sinp = (const float*)d_in[2];
    const float* Wq   = (const float*)d_in[4];
    const float* Wk   = (const float*)d_in[5];
    const float* Wv   = (const float*)d_in[6];
    const float* Avec = (const float*)d_in[7];
    const float* Wdt  = (const float*)d_in[8];
    const float* Wo   = (const float*)d_in[9];
    float* out = (float*)d_out;

    static cudaStream_t s1 = nullptr, s2 = nullptr;
    static cudaEvent_t eFork = nullptr, eS1 = nullptr, eS2 = nullptr, eRope = nullptr;
    if (s1 == nullptr) {
        cudaStreamCreateWithFlags(&s1, cudaStreamNonBlocking);
        cudaStreamCreateWithFlags(&s2, cudaStreamNonBlocking);
        cudaEventCreateWithFlags(&eFork, cudaEventDisableTiming);
        cudaEventCreateWithFlags(&eS1, cudaEventDisableTiming);
        cudaEventCreateWithFlags(&eS2, cudaEventDisableTiming);
        cudaEventCreateWithFlags(&eRope, cudaEventDisableTiming);
    }
    cudaStream_t s0 = 0;

    float *pqk, *pv, *phs, *pwqk, *pwo, *pattn;
    cudaGetSymbolAddress((void**)&pqk, g_qk);
    cudaGetSymbolAddress((void**)&pv, g_v);
    cudaGetSymbolAddress((void**)&phs, g_hs_t);
    cudaGetSymbolAddress((void**)&pwqk, g_wqk_t);
    cudaGetSymbolAddress((void**)&pwo, g_wo_t);
    cudaGetSymbolAddress((void**)&pattn, g_attn);
    uint16_t *hsh, *hsl, *wvh, *wvl;
    cudaGetSymbolAddress((void**)&hsh, g_hsh); cudaGetSymbolAddress((void**)&hsl, g_hsl);
    cudaGetSymbolAddress((void**)&wvh, g_wvh); cudaGetSymbolAddress((void**)&wvl, g_wvl);

    const int M = CB * CS;  // 4096

    // ---- fork ----
    cudaEventRecord(eFork, s0);
    cudaStreamWaitEvent(s1, eFork, 0);
    cudaStreamWaitEvent(s2, eFork, 0);

    // chain A (s0): q/k path
    launch_tf32r(s0, hs, phs, M * CHID);
    launch_tf32r(s0, Wq, pwqk, CQN * CHID);
    launch_tf32r(s0, Wk, pwqk + (size_t)1024 * CHID, CKN * CHID);
    launch_tgemm32(s0, phs, pwqk, pqk, M, CQK, CHID);
    rope_kernel<<<(CB * CS * (CH + CKVH) * 32) / 256, 256, 0, s0>>>(cosp, sinp);
    cudaEventRecord(eRope, s0);

    // chain B (s1): v path + dyn-mask pipeline + compaction
    launch_split(s1, hs, hsh, hsl, M * CHID);
    launch_split(s1, Wv, wvh, wvl, CKN * CHID);
    launch_bgemm(s1, hsh, hsl, wvh, wvl, pv, M, CKN, CHID);
    vtrans_kernel<<<dim3(CS / 32, CHD / 32, CB * CKVH), 256, 0, s1>>>();
    dt_kernel<<<M, 256, 0, s1>>>(Wdt, Avec);
    rate_kernel<<<CB * CH, 256, 0, s1>>>();
    cudaStreamWaitEvent(s1, eRope, 0);          // compaction needs rope's K splits
    compact_kernel<<<CBH, 256, 0, s1>>>();
    cudaEventRecord(eS1, s1);

    // chain C (s2): Wo prep
    launch_tf32r(s2, Wo, pwo, CHID * CQN);
    cudaEventRecord(eS2, s2);

    // ---- join for attention ----
    cudaStreamWaitEvent(s0, eS1, 0);
    cudaFuncSetAttribute(attn_mma_kernel, cudaFuncAttributeMaxDynamicSharedMemorySize, AT_SMEM);
    attn_mma_kernel<<<dim3(CS / QTR, CB * CH), 256, AT_SMEM, s0>>>();
    fixup_kernel<<<CB * CH, 256, 0, s0>>>();

    // ---- join Wo prep, output projection ----
    cudaStreamWaitEvent(s0, eS2, 0);
    launch_tgemm32(s0, pattn, pwo, out, M, CHID, CQN);
}

// round 13
// speedup vs baseline: 1.3115x; 1.3115x over previous
#include <cuda_runtime.h>
#include <cuda_bf16.h>
#include <math.h>
#include <float.h>
#include <stdint.h>

// ---------------- problem constants ----------------
#define CB    2
#define CS    2048
#define CHID  1024
#define CH    16
#define CKVH  8
#define CHD   64
#define CQN   (CH * CHD)      // 1024
#define CKN   (CKVH * CHD)    // 512
#define CQK   1536            // fused q|k projection width (tf32)
#define CSCALE 0.125f
#define CNEG  (-1000000000.0f)
#define KTH_IDX 715
#define QTR   128             // attention q-rows per CTA

// ---------------- scratch ----------------
__device__ float g_qk[CB * CS * CQK];
__device__ float g_v[CB * CS * CKN];
__device__ float g_q[CB * CS * CQN];
__device__ float g_k[CB * CS * CKN];
__device__ float g_attn[CB * CS * CQN];
__device__ float g_dyn[CB * CH * CS];
__device__ int   g_fu[CB * CH];

__device__ __align__(16) float g_hs_t[CB * CS * CHID];
__device__ __align__(16) float g_wqk_t[CQK * CHID];
__device__ __align__(16) float g_wo_t[CHID * CQN];
__device__ __align__(16) uint16_t g_hsh[CB * CS * CHID],   g_hsl[CB * CS * CHID];
__device__ __align__(16) uint16_t g_wvh[CKN * CHID],       g_wvl[CKN * CHID];
__device__ __align__(16) uint16_t g_qh[CB * CS * CQN],     g_ql[CB * CS * CQN];
__device__ __align__(16) uint16_t g_kh[CB * CS * CKN],     g_kl[CB * CS * CKN];
__device__ __align__(16) uint16_t g_vth[CB * CKVH * CHD * CS], g_vtl[CB * CKVH * CHD * CS];

// ================= helpers =================
__device__ __forceinline__ uint32_t smem_u32(const void* p) {
    uint32_t a;
    asm("{ .reg .u64 t; cvta.to.shared.u64 t, %1; cvt.u32.u64 %0, t; }" : "=r"(a) : "l"(p));
    return a;
}
__device__ __forceinline__ void ldm_x4(uint32_t* r, uint32_t addr) {
    asm volatile("ldmatrix.sync.aligned.m8n8.x4.shared.b16 {%0,%1,%2,%3}, [%4];"
                 : "=r"(r[0]), "=r"(r[1]), "=r"(r[2]), "=r"(r[3]) : "r"(addr));
}
__device__ __forceinline__ void mma_bf16(float* c, const uint32_t* a, const uint32_t* b) {
    asm volatile(
        "mma.sync.aligned.m16n8k16.row.col.f32.bf16.bf16.f32 "
        "{%0,%1,%2,%3}, {%4,%5,%6,%7}, {%8,%9}, {%0,%1,%2,%3};"
        : "+f"(c[0]), "+f"(c[1]), "+f"(c[2]), "+f"(c[3])
        : "r"(a[0]), "r"(a[1]), "r"(a[2]), "r"(a[3]), "r"(b[0]), "r"(b[1]));
}
__device__ __forceinline__ void mma_tf32(float* c, const uint32_t* a, const uint32_t* b) {
    asm volatile(
        "mma.sync.aligned.m16n8k8.row.col.f32.tf32.tf32.f32 "
        "{%0,%1,%2,%3}, {%4,%5,%6,%7}, {%8,%9}, {%0,%1,%2,%3};"
        : "+f"(c[0]), "+f"(c[1]), "+f"(c[2]), "+f"(c[3])
        : "r"(a[0]), "r"(a[1]), "r"(a[2]), "r"(a[3]), "r"(b[0]), "r"(b[1]));
}
__device__ __forceinline__ uint32_t bf2(float e0, float e1) {
    uint32_t r;
    asm("cvt.rn.bf16x2.f32 %0, %1, %2;" : "=r"(r) : "f"(e1), "f"(e0));
    return r;
}
__device__ __forceinline__ float hif_lo(uint32_t h) { return __uint_as_float(h << 16); }
__device__ __forceinline__ float hif_hi(uint32_t h) { return __uint_as_float(h & 0xFFFF0000u); }
__device__ __forceinline__ float tf32r(float x) {
    uint32_t r;
    asm("cvt.rna.tf32.f32 %0, %1;" : "=r"(r) : "f"(x));
    return __uint_as_float(r);
}
__device__ __forceinline__ void cpa16(uint32_t dst, const void* src) {
    asm volatile("cp.async.cg.shared.global [%0], [%1], 16;" :: "r"(dst), "l"(src));
}
#define CP_COMMIT() asm volatile("cp.async.commit_group;" ::: "memory")
#define CP_WAIT(n)  asm volatile("cp.async.wait_group %0;" :: "n"(n) : "memory")

// ---------------- elementwise prep kernels ----------------
__global__ void tf32r_kernel(const float4* __restrict__ src, float4* __restrict__ dst, int n4) {
    int i = blockIdx.x * blockDim.x + threadIdx.x;
    if (i >= n4) return;
    float4 v = src[i];
    dst[i] = make_float4(tf32r(v.x), tf32r(v.y), tf32r(v.z), tf32r(v.w));
}
__global__ void split_kernel(const float4* __restrict__ src,
                             uint2* __restrict__ hi, uint2* __restrict__ lo, int n4) {
    int i = blockIdx.x * blockDim.x + threadIdx.x;
    if (i >= n4) return;
    float4 v = src[i];
    uint32_t h0 = bf2(v.x, v.y), h1 = bf2(v.z, v.w);
    uint32_t l0 = bf2(v.x - hif_lo(h0), v.y - hif_hi(h0));
    uint32_t l1 = bf2(v.z - hif_lo(h1), v.w - hif_hi(h1));
    hi[i] = make_uint2(h0, h1);
    lo[i] = make_uint2(l0, l1);
}

// ============ single-pass TF32 GEMM, BK=16 ============
#define T32_TILE   10240
#define T32_STAGE  (2 * T32_TILE)
#define T32_SMEM   (2 * T32_STAGE)

__global__ void __launch_bounds__(256) tgemm32(const float* __restrict__ A,
                                               const float* __restrict__ W,
                                               float* __restrict__ C,
                                               int M, int N, int K) {
    extern __shared__ char sm[];
    const uint32_t sbase = smem_u32(sm);

    const int tid = threadIdx.x;
    const int wid = tid >> 5, lane = tid & 31;
    const int m0 = blockIdx.y * 128, n0 = blockIdx.x * 128;
    const int wm = wid & 1, wn = wid >> 1;

    const int lrow = tid >> 1;
    const int lh   = tid & 1;
    const size_t abase = (size_t)(m0 + lrow) * K + lh * 8;
    const size_t bbase = (size_t)(n0 + lrow) * K + lh * 8;
    const uint32_t doff = (uint32_t)(lrow * 80 + lh * 32);

    float acc[4][4][4];
#pragma unroll
    for (int i = 0; i < 4; ++i)
#pragma unroll
        for (int j = 0; j < 4; ++j)
#pragma unroll
            for (int q = 0; q < 4; ++q) acc[i][j][q] = 0.f;

    const int nchunk = K >> 4;

#define T32_STAGE_CHUNK(c, p)                                                  \
    do {                                                                       \
        const uint32_t d0 = sbase + (p) * T32_STAGE + doff;                    \
        const float* a_ = A + abase + (size_t)(c) * 16;                        \
        const float* b_ = W + bbase + (size_t)(c) * 16;                        \
        cpa16(d0, a_);              cpa16(d0 + 16, a_ + 4);                    \
        cpa16(d0 + T32_TILE, b_);   cpa16(d0 + T32_TILE + 16, b_ + 4);         \
    } while (0)

    T32_STAGE_CHUNK(0, 0);
    CP_COMMIT();

    for (int c = 0; c < nchunk; ++c) {
        const int p = c & 1;
        if (c + 1 < nchunk) {
            T32_STAGE_CHUNK(c + 1, p ^ 1);
            CP_COMMIT();
            CP_WAIT(1);
        } else {
            CP_WAIT(0);
        }
        __syncthreads();

        const uint32_t abuf = sbase + p * T32_STAGE;
        const uint32_t bbuf = abuf + T32_TILE;

        uint32_t bf[4][4];
#pragma unroll
        for (int nf = 0; nf < 4; ++nf) {
            const uint32_t rowb = (uint32_t)(wn * 32 + nf * 8 + (lane & 7));
            const uint32_t addr = bbuf + rowb * 80 + (uint32_t)(lane >> 3) * 16;
            ldm_x4(bf[nf], addr);
        }
#pragma unroll
        for (int ks = 0; ks < 2; ++ks) {
#pragma unroll
            for (int mf = 0; mf < 4; ++mf) {
                const uint32_t rowa = (uint32_t)(wm * 64 + mf * 16 + (lane & 15));
                const uint32_t addr = abuf + rowa * 80 + ks * 32 + (uint32_t)((lane >> 4) << 4);
                uint32_t af[4];
                ldm_x4(af, addr);
#pragma unroll
                for (int nf = 0; nf < 4; ++nf)
                    mma_tf32(acc[mf][nf], af, bf[nf] + ks * 2);
            }
        }
        __syncthreads();
    }

#pragma unroll
    for (int mf = 0; mf < 4; ++mf) {
        const int row = m0 + wm * 64 + mf * 16 + (lane >> 2);
#pragma unroll
        for (int nf = 0; nf < 4; ++nf) {
            const int col = n0 + wn * 32 + nf * 8 + (lane & 3) * 2;
            *(float2*)(C + (size_t)row * N + col)       = make_float2(acc[mf][nf][0], acc[mf][nf][1]);
            *(float2*)(C + (size_t)(row + 8) * N + col) = make_float2(acc[mf][nf][2], acc[mf][nf][3]);
        }
    }
}

// ============ bf16x3 GEMM (pre-split, cp.async) ============
#define BG_TILE   10240
#define BG_STAGE  (4 * BG_TILE)
#define BG_SMEM   (2 * BG_STAGE)

__global__ void __launch_bounds__(256) bgemm_nt(const uint16_t* __restrict__ Ah,
                                                const uint16_t* __restrict__ Al,
                                                const uint16_t* __restrict__ Bh,
                                                const uint16_t* __restrict__ Bl,
                                                float* __restrict__ C,
                                                int M, int N, int K) {
    extern __shared__ char sm[];
    const uint32_t sbase = smem_u32(sm);

    const int tid = threadIdx.x;
    const int wid = tid >> 5, lane = tid & 31;
    const int m0 = blockIdx.y * 128, n0 = blockIdx.x * 128;
    const int wm = wid & 1, wn = wid >> 1;

    const int lrow = tid >> 1;
    const int lh   = tid & 1;
    const size_t abase = (size_t)(m0 + lrow) * K + lh * 16;
    const size_t bbase = (size_t)(n0 + lrow) * K + lh * 16;
    const uint32_t doff = (uint32_t)(lrow * 80 + lh * 32);

    float acc[4][4][4];
#pragma unroll
    for (int i = 0; i < 4; ++i)
#pragma unroll
        for (int j = 0; j < 4; ++j)
#pragma unroll
            for (int q = 0; q < 4; ++q) acc[i][j][q] = 0.f;

    const int nchunk = K >> 5;

#define BG_STAGE_CHUNK(c, p)                                                   \
    do {                                                                       \
        const uint32_t d0 = sbase + (p) * BG_STAGE + doff;                     \
        const uint16_t* a_h = Ah + abase + (size_t)(c) * 32;                   \
        const uint16_t* a_l = Al + abase + (size_t)(c) * 32;                   \
        const uint16_t* b_h = Bh + bbase + (size_t)(c) * 32;                   \
        const uint16_t* b_l = Bl + bbase + (size_t)(c) * 32;                   \
        cpa16(d0, a_h);                  cpa16(d0 + 16, a_h + 8);              \
        cpa16(d0 + BG_TILE, a_l);        cpa16(d0 + BG_TILE + 16, a_l + 8);    \
        cpa16(d0 + 2 * BG_TILE, b_h);    cpa16(d0 + 2 * BG_TILE + 16, b_h + 8);\
        cpa16(d0 + 3 * BG_TILE, b_l);    cpa16(d0 + 3 * BG_TILE + 16, b_l + 8);\
    } while (0)

    BG_STAGE_CHUNK(0, 0);
    CP_COMMIT();

    for (int c = 0; c < nchunk; ++c) {
        const int p = c & 1;
        if (c + 1 < nchunk) {
            BG_STAGE_CHUNK(c + 1, p ^ 1);
            CP_COMMIT();
            CP_WAIT(1);
        } else {
            CP_WAIT(0);
        }
        __syncthreads();

        const uint32_t buf = sbase + p * BG_STAGE;
#pragma unroll
        for (int ks = 0; ks < 2; ++ks) {
            const int kk = ks * 16;
            uint32_t bh[4][2], bl[4][2];
#pragma unroll
            for (int half = 0; half < 2; ++half) {
                const int n = wn * 32 + half * 16;
                const uint32_t rowb = (uint32_t)(n + (lane & 7) + ((lane & 16) >> 1));
                const uint32_t colb = (uint32_t)(kk + (lane & 8));
                const uint32_t addr = buf + 2 * BG_TILE + rowb * 80 + colb * 2;
                uint32_t r[4];
                ldm_x4(r, addr);
                bh[half * 2][0] = r[0]; bh[half * 2][1] = r[1];
                bh[half * 2 + 1][0] = r[2]; bh[half * 2 + 1][1] = r[3];
                ldm_x4(r, addr + BG_TILE);
                bl[half * 2][0] = r[0]; bl[half * 2][1] = r[1];
                bl[half * 2 + 1][0] = r[2]; bl[half * 2 + 1][1] = r[3];
            }
#pragma unroll
            for (int mf = 0; mf < 4; ++mf) {
                const int m = wm * 64 + mf * 16;
                const uint32_t rowa = (uint32_t)(m + (lane & 15));
                const uint32_t cola = (uint32_t)(kk + ((lane >> 4) << 3));
                const uint32_t addr = buf + rowa * 80 + cola * 2;
                uint32_t ah4[4], al4[4];
                ldm_x4(ah4, addr);
                ldm_x4(al4, addr + BG_TILE);
#pragma unroll
                for (int nf = 0; nf < 4; ++nf) {
                    mma_bf16(acc[mf][nf], ah4, bh[nf]);
                    mma_bf16(acc[mf][nf], ah4, bl[nf]);
                    mma_bf16(acc[mf][nf], al4, bh[nf]);
                }
            }
        }
        __syncthreads();
    }

#pragma unroll
    for (int mf = 0; mf < 4; ++mf) {
        const int row = m0 + wm * 64 + mf * 16 + (lane >> 2);
#pragma unroll
        for (int nf = 0; nf < 4; ++nf) {
            const int col = n0 + wn * 32 + nf * 8 + (lane & 3) * 2;
            *(float2*)(C + (size_t)row * N + col)       = make_float2(acc[mf][nf][0], acc[mf][nf][1]);
            *(float2*)(C + (size_t)(row + 8) * N + col) = make_float2(acc[mf][nf][2], acc[mf][nf][3]);
        }
    }
}

// ---------------- V transpose + split ----------------
__global__ void __launch_bounds__(256) vtrans_kernel() {
    __shared__ float t[32][33];
    const int bk = blockIdx.z, b = bk >> 3, kvh = bk & 7;
    const int s0 = blockIdx.x * 32, d0 = blockIdx.y * 32;
    const int x = threadIdx.x & 31, y = threadIdx.x >> 5;
#pragma unroll
    for (int j = 0; j < 4; ++j) {
        int s = s0 + y + j * 8;
        t[y + j * 8][x] = g_v[((size_t)(b * CS + s)) * CKN + kvh * CHD + d0 + x];
    }
    __syncthreads();
#pragma unroll
    for (int j = 0; j < 4; ++j) {
        int d = d0 + y + j * 8;
        float v = t[x][y + j * 8];
        uint32_t hv = bf2(v, 0.f);
        uint32_t lv = bf2(v - hif_lo(hv), 0.f);
        size_t idx = (((size_t)(b * CKVH + kvh)) * CHD + d) * CS + s0 + x;
        g_vth[idx] = (uint16_t)(hv & 0xFFFFu);
        g_vtl[idx] = (uint16_t)(lv & 0xFFFFu);
    }
}

// ---------------- RoPE ----------------
__global__ void rope_kernel(const float* __restrict__ cosp,
                            const float* __restrict__ sinp) {
    int idx = blockIdx.x * blockDim.x + threadIdx.x;
    int d  = idx & 31;
    int t  = idx >> 5;
    int hh = t % 24;
    int t2 = t / 24;
    int s  = t2 % CS;
    int b  = t2 / CS;

    const float* cb = cosp + ((size_t)b * CS + s) * CHD;
    const float* sb = sinp + ((size_t)b * CS + s) * CHD;
    float c1 = cb[d],      s1 = sb[d];
    float c2 = cb[d + 32], s2 = sb[d + 32];

    const float* src;
    float* dst;
    uint16_t *bh, *bl;
    const size_t row = ((size_t)b * CS + s) * CQK;
    if (hh < CH) {
        src = g_qk + row + hh * CHD;
        size_t off = ((size_t)b * CS + s) * CQN + hh * CHD;
        dst = g_q + off; bh = g_qh + off; bl = g_ql + off;
    } else {
        src = g_qk + row + 1024 + (hh - CH) * CHD;
        size_t off = ((size_t)b * CS + s) * CKN + (hh - CH) * CHD;
        dst = g_k + off; bh = g_kh + off; bl = g_kl + off;
    }

    float x1 = src[d];
    float x2 = src[d + 32];
    float y1 = x1 * c1 - x2 * s1;
    float y2 = x2 * c2 + x1 * s2;
    dst[d]      = y1;
    dst[d + 32] = y2;

    uint32_t h1 = bf2(y1, 0.f);
    uint32_t h2 = bf2(y2, 0.f);
    bh[d]      = (uint16_t)(h1 & 0xFFFFu);
    bh[d + 32] = (uint16_t)(h2 & 0xFFFFu);
    bl[d]      = (uint16_t)(bf2(y1 - hif_lo(h1), 0.f) & 0xFFFFu);
    bl[d + 32] = (uint16_t)(bf2(y2 - hif_lo(h2), 0.f) & 0xFFFFu);
}

// ---------------- dt -> dyn ----------------
__global__ void __launch_bounds__(256) dt_kernel(const float* __restrict__ Wdt,
                                                 const float* __restrict__ Avec) {
    __shared__ float vsh[CKN];
    int bs = blockIdx.x;
    int b = bs / CS, s = bs % CS;
    int tid = threadIdx.x;
    vsh[tid]        = g_v[(size_t)bs * CKN + tid];
    vsh[tid + 256]  = g_v[(size_t)bs * CKN + tid + 256];
    __syncthreads();

    int warp = tid >> 5, lane = tid & 31;
    for (int h = warp; h < CH; h += 8) {
        const float* wrow = Wdt + (size_t)h * CKN;
        float acc = 0.f;
        for (int j = lane; j < CKN; j += 32) acc = fmaf(vsh[j], wrow[j], acc);
#pragma unroll
        for (int off = 16; off > 0; off >>= 1)
            acc += __shfl_down_sync(0xffffffffu, acc, off);
        if (lane == 0) {
            float x = acc;
            float sp = fmaxf(x, 0.f) + log1pf(expf(-fabsf(x)));
            g_dyn[((size_t)b * CH + h) * CS + s] = expf(Avec[h] * sp);
        }
    }
}

// ---------------- rate kernel ----------------
__global__ void __launch_bounds__(256) rate_kernel() {
    __shared__ float sv[CS];
    __shared__ float s_rate;
    __shared__ int   s_fu;
    int bh = blockIdx.x;
    int tid = threadIdx.x;
    float* dptr = g_dyn + (size_t)bh * CS;

    for (int i = tid; i < CS; i += 256) sv[i] = dptr[i];
    __syncthreads();

    for (int k = 2; k <= CS; k <<= 1) {
        for (int j = k >> 1; j > 0; j >>= 1) {
            for (int i = tid; i < CS; i += 256) {
                int ixj = i ^ j;
                if (ixj > i) {
                    float a = sv[i], c = sv[ixj];
                    bool up = ((i & k) == 0);
                    if (up ? (a > c) : (a < c)) { sv[i] = c; sv[ixj] = a; }
                }
            }
            __syncthreads();
        }
    }
    if (tid == 0) { s_rate = sv[KTH_IDX]; s_fu = CS; }
    __syncthreads();

    float rate = s_rate;
    for (int i = tid; i < CS; i += 256) {
        float m = dptr[i];
        if (m < rate) dptr[i] = -FLT_MAX;
        else          atomicMin(&s_fu, i);
    }
    __syncthreads();
    if (tid == 0) g_fu[bh] = s_fu;
}

// ---------------- attention: 256 threads, q-tile 128, forced 2 CTAs/SM ----------------
#define AT_SMEM 74240

__global__ void __launch_bounds__(256, 2) attn_mma_kernel() {
    extern __shared__ char asmem[];
    const uint32_t ksb = smem_u32(asmem);
    const uint32_t vsb = ksb + 36864;
    float* smb = (float*)(asmem + 73728);

    const int tid = threadIdx.x, lane = tid & 31, w = tid >> 5;
    const int qt = (CS / QTR - 1) - blockIdx.x;
    const int bh = blockIdx.y;
    const int b = bh >> 4, h = bh & 15, kvh = h >> 1;
    const int nkt = 2 * qt + 2;

    const int srow = tid & 63, part4 = tid >> 6;
    const uint32_t soff = (uint32_t)(srow * 144 + part4 * 32);

    const uint16_t* ksrc_h = g_kh + ((size_t)(b * CS + srow)) * CKN + kvh * CHD + part4 * 16;
    const uint16_t* ksrc_l = g_kl + ((size_t)(b * CS + srow)) * CKN + kvh * CHD + part4 * 16;
    const uint16_t* vsrc_h = g_vth + (((size_t)(b * CKVH + kvh)) * CHD + srow) * CS + part4 * 16;
    const uint16_t* vsrc_l = g_vtl + (((size_t)(b * CKVH + kvh)) * CHD + srow) * CS + part4 * 16;

#define AT_STAGE_KV(kt, p)                                                        \
    do {                                                                          \
        const uint16_t* kh_ = ksrc_h + (size_t)(kt) * 64 * CKN;                   \
        const uint16_t* kl_ = ksrc_l + (size_t)(kt) * 64 * CKN;                   \
        const uint16_t* vh_ = vsrc_h + (kt) * 64;                                 \
        const uint16_t* vl_ = vsrc_l + (kt) * 64;                                 \
        uint32_t kd = ksb + (p) * 18432 + soff;                                   \
        uint32_t vd = vsb + (p) * 18432 + soff;                                   \
        cpa16(kd, kh_);         cpa16(kd + 16, kh_ + 8);                          \
        cpa16(kd + 9216, kl_);  cpa16(kd + 9216 + 16, kl_ + 8);                   \
        cpa16(vd, vh_);         cpa16(vd + 16, vh_ + 8);                          \
        cpa16(vd + 9216, vl_);  cpa16(vd + 9216 + 16, vl_ + 8);                   \
    } while (0)

    {
        const int qrow = tid >> 1, qpart = tid & 1;
        const uint32_t qoff = (uint32_t)(qrow * 144 + qpart * 64);
        const uint16_t* qh_ = g_qh + ((size_t)(b * CS + qt * QTR + qrow)) * CQN + h * CHD + qpart * 32;
        const uint16_t* ql_ = g_ql + ((size_t)(b * CS + qt * QTR + qrow)) * CQN + h * CHD + qpart * 32;
        uint32_t qdh = ksb + 18432 + qoff;
        uint32_t qdl = vsb + 18432 + qoff;
        cpa16(qdh, qh_);        cpa16(qdh + 16, qh_ + 8);
        cpa16(qdh + 32, qh_ + 16); cpa16(qdh + 48, qh_ + 24);
        cpa16(qdl, ql_);        cpa16(qdl + 16, ql_ + 8);
        cpa16(qdl + 32, ql_ + 16); cpa16(qdl + 48, ql_ + 24);
    }
    AT_STAGE_KV(0, 0);
    CP_COMMIT();
    if (tid < 64) smb[tid] = g_dyn[(size_t)bh * CS + tid];
    CP_WAIT(0);
    __syncthreads();

    uint32_t qhf[4][4], qlf[4][4];
    {
        const uint32_t rowa = (uint32_t)(w * 16 + (lane & 15));
        const uint32_t cola0 = (uint32_t)((lane >> 4) << 3);
#pragma unroll
        for (int ks = 0; ks < 4; ++ks) {
            const uint32_t off = rowa * 144 + (ks * 16 + cola0) * 2;
            ldm_x4(qhf[ks], ksb + 18432 + off);
            ldm_x4(qlf[ks], vsb + 18432 + off);
        }
    }
    __syncthreads();

    float oacc[8][4];
#pragma unroll
    for (int nf = 0; nf < 8; ++nf)
#pragma unroll
        for (int j = 0; j < 4; ++j) oacc[nf][j] = 0.f;

    float mrun0 = -1e30f, mrun1 = -1e30f, lrun0 = 0.f, lrun1 = 0.f;
    const int row0 = lane >> 2;
    const int qi0 = w * 16 + row0, qi1 = qi0 + 8;

    for (int kt = 0; kt < nkt; ++kt) {
        const int p = kt & 1;
        if (kt + 1 < nkt) {
            AT_STAGE_KV(kt + 1, p ^ 1);
            CP_COMMIT();
            if (tid < 64) smb[(p ^ 1) * 64 + tid] = g_dyn[(size_t)bh * CS + (kt + 1) * 64 + tid];
            CP_WAIT(1);
        } else {
            CP_WAIT(0);
        }
        __syncthreads();

        const uint32_t kbuf = ksb + p * 18432;
        const uint32_t vbuf = vsb + p * 18432;
        const float* mbp = smb + p * 64;

        float sc[8][4];
#pragma unroll
        for (int nf = 0; nf < 8; ++nf)
#pragma unroll
            for (int j = 0; j < 4; ++j) sc[nf][j] = 0.f;

#pragma unroll
        for (int ks = 0; ks < 4; ++ks) {
#pragma unroll
            for (int g = 0; g < 4; ++g) {
                const uint32_t rowb = (uint32_t)(g * 16 + (lane & 7) + ((lane & 16) >> 1));
                const uint32_t colb = (uint32_t)(ks * 16 + (lane & 8));
                const uint32_t addr = kbuf + rowb * 144 + colb * 2;
                uint32_t kh4[4], kl4[4];
                ldm_x4(kh4, addr);
                ldm_x4(kl4, addr + 9216);
                mma_bf16(sc[2 * g],     qhf[ks], kh4);
                mma_bf16(sc[2 * g],     qhf[ks], kl4);
                mma_bf16(sc[2 * g],     qlf[ks], kh4);
                mma_bf16(sc[2 * g + 1], qhf[ks], kh4 + 2);
                mma_bf16(sc[2 * g + 1], qhf[ks], kl4 + 2);
                mma_bf16(sc[2 * g + 1], qlf[ks], kh4 + 2);
            }
        }

        const bool diag = (kt >= 2 * qt);
        const int koff = (kt - 2 * qt) * 64;
        float mx0 = -1e30f, mx1 = -1e30f;
#pragma unroll
        for (int nf = 0; nf < 8; ++nf) {
            const int c0 = nf * 8 + (lane & 3) * 2;
            const float b0 = mbp[c0], b1 = mbp[c0 + 1];
            float s00 = sc[nf][0] * CSCALE + b0;
            float s01 = sc[nf][1] * CSCALE + b1;
            float s10 = sc[nf][2] * CSCALE + b0;
            float s11 = sc[nf][3] * CSCALE + b1;
            if (diag) {
                if (koff + c0 > qi0)     s00 = -FLT_MAX;
                if (koff + c0 + 1 > qi0) s01 = -FLT_MAX;
                if (koff + c0 > qi1)     s10 = -FLT_MAX;
                if (koff + c0 + 1 > qi1) s11 = -FLT_MAX;
            }
            sc[nf][0] = s00; sc[nf][1] = s01; sc[nf][2] = s10; sc[nf][3] = s11;
            mx0 = fmaxf(mx0, fmaxf(s00, s01));
            mx1 = fmaxf(mx1, fmaxf(s10, s11));
        }
        mx0 = fmaxf(mx0, __shfl_xor_sync(0xffffffffu, mx0, 1));
        mx0 = fmaxf(mx0, __shfl_xor_sync(0xffffffffu, mx0, 2));
        mx1 = fmaxf(mx1, __shfl_xor_sync(0xffffffffu, mx1, 1));
        mx1 = fmaxf(mx1, __shfl_xor_sync(0xffffffffu, mx1, 2));

        const float mn0 = fmaxf(mrun0, mx0), mn1 = fmaxf(mrun1, mx1);
        const float esc0 = __expf(mrun0 - mn0), esc1 = __expf(mrun1 - mn1);
        mrun0 = mn0; mrun1 = mn1;

        float sum0 = 0.f, sum1 = 0.f;
#pragma unroll
        for (int nf = 0; nf < 8; ++nf) {
            float p00 = __expf(sc[nf][0] - mn0);
            float p01 = __expf(sc[nf][1] - mn0);
            float p10 = __expf(sc[nf][2] - mn1);
            float p11 = __expf(sc[nf][3] - mn1);
            sc[nf][0] = p00; sc[nf][1] = p01; sc[nf][2] = p10; sc[nf][3] = p11;
            sum0 += p00 + p01;
            sum1 += p10 + p11;
        }
        sum0 += __shfl_xor_sync(0xffffffffu, sum0, 1);
        sum0 += __shfl_xor_sync(0xffffffffu, sum0, 2);
        sum1 += __shfl_xor_sync(0xffffffffu, sum1, 1);
        sum1 += __shfl_xor_sync(0xffffffffu, sum1, 2);
        lrun0 = lrun0 * esc0 + sum0;
        lrun1 = lrun1 * esc1 + sum1;

#pragma unroll
        for (int nf = 0; nf < 8; ++nf) {
            oacc[nf][0] *= esc0; oacc[nf][1] *= esc0;
            oacc[nf][2] *= esc1; oacc[nf][3] *= esc1;
        }

#pragma unroll
        for (int ks = 0; ks < 4; ++ks) {
            uint32_t ah4[4], al4[4];
            ah4[0] = bf2(sc[2 * ks][0], sc[2 * ks][1]);
            ah4[1] = bf2(sc[2 * ks][2], sc[2 * ks][3]);
            ah4[2] = bf2(sc[2 * ks + 1][0], sc[2 * ks + 1][1]);
            ah4[3] = bf2(sc[2 * ks + 1][2], sc[2 * ks + 1][3]);
            al4[0] = bf2(sc[2 * ks][0] - hif_lo(ah4[0]), sc[2 * ks][1] - hif_hi(ah4[0]));
            al4[1] = bf2(sc[2 * ks][2] - hif_lo(ah4[1]), sc[2 * ks][3] - hif_hi(ah4[1]));
            al4[2] = bf2(sc[2 * ks + 1][0] - hif_lo(ah4[2]), sc[2 * ks + 1][1] - hif_hi(ah4[2]));
            al4[3] = bf2(sc[2 * ks + 1][2] - hif_lo(ah4[3]), sc[2 * ks + 1][3] - hif_hi(ah4[3]));
#pragma unroll
            for (int g = 0; g < 4; ++g) {
                const uint32_t rowb = (uint32_t)(g * 16 + (lane & 7) + ((lane & 16) >> 1));
                const uint32_t colb = (uint32_t)(ks * 16 + (lane & 8));
                const uint32_t addr = vbuf + rowb * 144 + colb * 2;
                uint32_t vh4[4], vl4[4];
                ldm_x4(vh4, addr);
                ldm_x4(vl4, addr + 9216);
                mma_bf16(oacc[2 * g],     ah4, vh4);
                mma_bf16(oacc[2 * g],     ah4, vl4);
                mma_bf16(oacc[2 * g],     al4, vh4);
                mma_bf16(oacc[2 * g + 1], ah4, vh4 + 2);
                mma_bf16(oacc[2 * g + 1], ah4, vl4 + 2);
                mma_bf16(oacc[2 * g + 1], al4, vh4 + 2);
            }
        }
        __syncthreads();
    }

    const float inv0 = 1.f / lrun0, inv1 = 1.f / lrun1;
    const int grow0 = qt * QTR + w * 16 + row0;
    float* ob0 = g_attn + ((size_t)(b * CS + grow0)) * CQN + h * CHD;
    float* ob1 = g_attn + ((size_t)(b * CS + grow0 + 8)) * CQN + h * CHD;
#pragma unroll
    for (int nf = 0; nf < 8; ++nf) {
        const int col = nf * 8 + (lane & 3) * 2;
        *(float2*)(ob0 + col) = make_float2(tf32r(oacc[nf][0] * inv0), tf32r(oacc[nf][1] * inv0));
        *(float2*)(ob1 + col) = make_float2(tf32r(oacc[nf][2] * inv1), tf32r(oacc[nf][3] * inv1));
    }
}

// ---------------- exact full-row fixup ----------------
__global__ void __launch_bounds__(256) fixup_kernel() {
    __shared__ float qrow[CHD];
    __shared__ float s_sh[CS];
    __shared__ float red[256];
    __shared__ float s_max, s_den;

    int bh = blockIdx.x;
    int b = bh >> 4, h = bh & 15, kvh = h >> 1;
    int tid = threadIdx.x;
    int fu = g_fu[bh];
    if (fu <= 0) return;

    for (int qi = 0; qi < fu; ++qi) {
        if (tid < CHD) qrow[tid] = g_q[((size_t)(b * CS + qi)) * CQN + h * CHD + tid];
        __syncthreads();

        float lm = -FLT_MAX;
        for (int ki = tid; ki < CS; ki += 256) {
            const float* krow = g_k + ((size_t)(b * CS + ki)) * CKN + kvh * CHD;
            float dot = 0.f;
#pragma unroll 16
            for (int d = 0; d < CHD; ++d) dot = fmaf(qrow[d], krow[d], dot);
            float mv = g_dyn[(size_t)bh * CS + ki] + ((ki <= qi) ? 0.0f : CNEG);
            float sc = dot * CSCALE + mv;
            s_sh[ki] = sc;
            lm = fmaxf(lm, sc);
        }
        red[tid] = lm;
        __syncthreads();
        for (int off = 128; off > 0; off >>= 1) {
            if (tid < off) red[tid] = fmaxf(red[tid], red[tid + off]);
            __syncthreads();
        }
        if (tid == 0) s_max = red[0];
        __syncthreads();

        float ls = 0.f;
        float rmax = s_max;
        for (int ki = tid; ki < CS; ki += 256) {
            float w2 = expf(s_sh[ki] - rmax);
            s_sh[ki] = w2;
            ls += w2;
        }
        red[tid] = ls;
        __syncthreads();
        for (int off = 128; off > 0; off >>= 1) {
            if (tid < off) red[tid] += red[tid + off];
            __syncthreads();
        }
        if (tid == 0) s_den = red[0];
        __syncthreads();

        int d = tid & 63, part = tid >> 6;
        float oacc = 0.f;
        for (int ki = part; ki < CS; ki += 4)
            oacc = fmaf(s_sh[ki], g_v[((size_t)(b * CS + ki)) * CKN + kvh * CHD + d], oacc);
        red[tid] = oacc;
        __syncthreads();
        if (tid < 64) {
            float tot = (red[tid] + red[tid + 64] + red[tid + 128] + red[tid + 192]) / s_den;
            g_attn[((size_t)(b * CS + qi)) * CQN + h * CHD + d] = tf32r(tot);
        }
        __syncthreads();
    }
}

// ---------------- host launcher (forked-stream graph) ----------------
static void launch_tgemm32(cudaStream_t st, const float* A, const float* W, float* C,
                           int M, int N, int K) {
    cudaFuncSetAttribute(tgemm32, cudaFuncAttributeMaxDynamicSharedMemorySize, T32_SMEM);
    tgemm32<<<dim3(N / 128, M / 128), 256, T32_SMEM, st>>>(A, W, C, M, N, K);
}
static void launch_bgemm(cudaStream_t st, const uint16_t* Ah, const uint16_t* Al,
                         const uint16_t* Bh, const uint16_t* Bl,
                         float* C, int M, int N, int K) {
    cudaFuncSetAttribute(bgemm_nt, cudaFuncAttributeMaxDynamicSharedMemorySize, BG_SMEM);
    bgemm_nt<<<dim3(N / 128, M / 128), 256, BG_SMEM, st>>>(Ah, Al, Bh, Bl, C, M, N, K);
}
static void launch_tf32r(cudaStream_t st, const float* src, float* dst, int n) {
    int n4 = n / 4;
    tf32r_kernel<<<(n4 + 255) / 256, 256, 0, st>>>((const float4*)src, (float4*)dst, n4);
}
static void launch_split(cudaStream_t st, const float* src, uint16_t* hi, uint16_t* lo, int n) {
    int n4 = n / 4;
    split_kernel<<<(n4 + 255) / 256, 256, 0, st>>>((const float4*)src, (uint2*)hi, (uint2*)lo, n4);
}

extern "C" void kernel_launch(void* const* d_in, const int* in_sizes, int n_in,
                              void* d_out, int out_size) {
    const float* hs   = (const float*)d_in[0];
    const float* cosp = (const float*)d_in[1];
    const float* sinp = (const float*)d_in[2];
    const float* Wq   = (const float*)d_in[4];
    const float* Wk   = (const float*)d_in[5];
    const float* Wv   = (const float*)d_in[6];
    const float* Avec = (const float*)d_in[7];
    const float* Wdt  = (const float*)d_in[8];
    const float* Wo   = (const float*)d_in[9];
    float* out = (float*)d_out;

    static cudaStream_t s1 = nullptr, s2 = nullptr;
    static cudaEvent_t eFork = nullptr, eS1 = nullptr, eS2 = nullptr;
    if (s1 == nullptr) {
        cudaStreamCreateWithFlags(&s1, cudaStreamNonBlocking);
        cudaStreamCreateWithFlags(&s2, cudaStreamNonBlocking);
        cudaEventCreateWithFlags(&eFork, cudaEventDisableTiming);
        cudaEventCreateWithFlags(&eS1, cudaEventDisableTiming);
        cudaEventCreateWithFlags(&eS2, cudaEventDisableTiming);
    }
    cudaStream_t s0 = 0;

    float *pqk, *pv, *phs, *pwqk, *pwo, *pattn;
    cudaGetSymbolAddress((void**)&pqk, g_qk);
    cudaGetSymbolAddress((void**)&pv, g_v);
    cudaGetSymbolAddress((void**)&phs, g_hs_t);
    cudaGetSymbolAddress((void**)&pwqk, g_wqk_t);
    cudaGetSymbolAddress((void**)&pwo, g_wo_t);
    cudaGetSymbolAddress((void**)&pattn, g_attn);
    uint16_t *hsh, *hsl, *wvh, *wvl;
    cudaGetSymbolAddress((void**)&hsh, g_hsh); cudaGetSymbolAddress((void**)&hsl, g_hsl);
    cudaGetSymbolAddress((void**)&wvh, g_wvh); cudaGetSymbolAddress((void**)&wvl, g_wvl);

    const int M = CB * CS;  // 4096

    // ---- fork ----
    cudaEventRecord(eFork, s0);
    cudaStreamWaitEvent(s1, eFork, 0);
    cudaStreamWaitEvent(s2, eFork, 0);

    // chain A (s0): q/k path
    launch_tf32r(s0, hs, phs, M * CHID);
    launch_tf32r(s0, Wq, pwqk, CQN * CHID);
    launch_tf32r(s0, Wk, pwqk + (size_t)1024 * CHID, CKN * CHID);
    launch_tgemm32(s0, phs, pwqk, pqk, M, CQK, CHID);
    rope_kernel<<<(CB * CS * (CH + CKVH) * 32) / 256, 256, 0, s0>>>(cosp, sinp);

    // chain B (s1): v path + dyn-mask pipeline
    launch_split(s1, hs, hsh, hsl, M * CHID);
    launch_split(s1, Wv, wvh, wvl, CKN * CHID);
    launch_bgemm(s1, hsh, hsl, wvh, wvl, pv, M, CKN, CHID);
    vtrans_kernel<<<dim3(CS / 32, CHD / 32, CB * CKVH), 256, 0, s1>>>();
    dt_kernel<<<M, 256, 0, s1>>>(Wdt, Avec);
    rate_kernel<<<CB * CH, 256, 0, s1>>>();
    cudaEventRecord(eS1, s1);

    // chain C (s2): Wo prep
    launch_tf32r(s2, Wo, pwo, CHID * CQN);
    cudaEventRecord(eS2, s2);

    // ---- join for attention ----
    cudaStreamWaitEvent(s0, eS1, 0);
    cudaFuncSetAttribute(attn_mma_kernel, cudaFuncAttributeMaxDynamicSharedMemorySize, AT_SMEM);
    attn_mma_kernel<<<dim3(CS / QTR, CB * CH), 256, AT_SMEM, s0>>>();
    fixup_kernel<<<CB * CH, 256, 0, s0>>>();

    // ---- join Wo prep, output projection ----
    cudaStreamWaitEvent(s0, eS2, 0);
    launch_tgemm32(s0, pattn, pwo, out, M, CHID, CQN);
}